// round 17
// baseline (speedup 1.0000x reference)
#include <cuda_runtime.h>
#include <cuda_fp16.h>
#include <stdint.h>
#include <math.h>

#define MAXN 131072

// ---------------- device scratch ----------------
__device__ __half g_hin [(size_t)MAXN * 32];
__device__ __half g_actA[(size_t)MAXN * 512];
__device__ __half g_actB[(size_t)MAXN * 512];
__device__ float  g_cs  [(size_t)MAXN * 32];
__device__ __half g_w0c [32 * 512];             // [K=32][N=512], k>=8 zero
__device__ __half g_w1c [512 * 512];            // [K][N]
__device__ __half g_w2c [512 * 512];
__device__ __half g_w3c [512 * 512];
__device__ __half g_wcc [512 * 32];             // [K=512][N=32], n>=27 zero

// ---------------- weight conversion ----------------
__global__ void convert_weights_kernel(const float* __restrict__ w0, const float* __restrict__ w1,
                                       const float* __restrict__ w2, const float* __restrict__ w3,
                                       const float* __restrict__ wc) {
    int i = blockIdx.x * blockDim.x + threadIdx.x;
    if (i < 512 * 512) {
        g_w1c[i] = __float2half(w1[i]);
        g_w2c[i] = __float2half(w2[i]);
        g_w3c[i] = __float2half(w3[i]);
    }
    if (i < 32 * 512) {
        int k = i / 512;
        g_w0c[i] = (k < 8) ? __float2half(w0[i]) : __float2half(0.0f);
    }
    if (i < 512 * 32) {
        int k = i / 32, n = i % 32;
        g_wcc[i] = (n < 27) ? __float2half(wc[k * 27 + n]) : __float2half(0.0f);
    }
}

// ---------------- hin: MLP input + albedo ----------------
__global__ void __launch_bounds__(256) hin_kernel(
    const float* __restrict__ normals, const float* __restrict__ viewd,
    const float* __restrict__ feat, float* __restrict__ out, int N)
{
    int p = blockIdx.x * 256 + threadIdx.x;
    if (p >= N) return;
    float nx = normals[3 * p + 0], ny = normals[3 * p + 1], nz = normals[3 * p + 2];
    float vx = viewd[3 * p + 0],  vy = viewd[3 * p + 1],  vz = viewd[3 * p + 2];
    const float* f = feat + (size_t)p * 16;
    float fr = f[0];
    float rough = (fr > 0.0f) ? (fr + log1pf(expf(-fr))) : log1pf(expf(fr));
    float dt = nx * vx + ny * vy + nz * vz;

    float a0 = 1.0f / (1.0f + expf(-f[10]));
    float a1 = 1.0f / (1.0f + expf(-f[11]));
    float a2 = 1.0f / (1.0f + expf(-f[12]));
    size_t N3 = (size_t)N * 3;
    out[N3 + 3 * p + 0] = a0; out[N3 + 3 * p + 1] = a1; out[N3 + 3 * p + 2] = a2;

    __half2 h01 = __floats2half2_rn(dt, vx);
    __half2 h23 = __floats2half2_rn(vy, vz);
    __half2 h45 = __floats2half2_rn(nx, ny);
    __half2 h67 = __floats2half2_rn(nz, rough);
    uint4* hp = reinterpret_cast<uint4*>(g_hin + (size_t)p * 32);
    hp[0] = make_uint4(*(uint32_t*)&h01, *(uint32_t*)&h23, *(uint32_t*)&h45, *(uint32_t*)&h67);
    hp[1] = make_uint4(0, 0, 0, 0);
    hp[2] = make_uint4(0, 0, 0, 0);
    hp[3] = make_uint4(0, 0, 0, 0);
}

// ---------------- prep_fused: SH weights + ref_SH dot in one pass ----------------
// One thread per point; ref_SH streamed by l-chunk through smem (coalesced).
#define PF_PTS 256
#define PF_SMEM (PF_PTS * 63 * 4)   // l=10 chunk: 63 floats/pt

__global__ void __launch_bounds__(256, 2) prep_fused_kernel(
    const float* __restrict__ normals, const float* __restrict__ viewd,
    const float* __restrict__ feat, const float* __restrict__ refsh,
    float* __restrict__ out, int N)
{
    extern __shared__ float stage[];

    const int tid = threadIdx.x;
    const int p = blockIdx.x * PF_PTS + tid;
    const bool valid = (p < N);

    float nx = 0.f, ny = 0.f, nz = 1.f, vx = 0.f, vy = 0.f, vz = 1.f;
    float fr = 0.f, f10 = 0.f, f11 = 0.f, f12 = 0.f;
    if (valid) {
        nx = normals[3 * p + 0]; ny = normals[3 * p + 1]; nz = normals[3 * p + 2];
        vx = viewd[3 * p + 0];   vy = viewd[3 * p + 1];   vz = viewd[3 * p + 2];
        const float* f = feat + (size_t)p * 16;
        fr = f[0]; f10 = f[10]; f11 = f[11]; f12 = f[12];
    }
    float rough = (fr > 0.0f) ? (fr + log1pf(expf(-fr))) : log1pf(expf(fr));
    float dt = nx * vx + ny * vy + nz * vz;
    float wx = 2.0f * nx * dt - vx, wy = 2.0f * ny * dt - vy, wz = 2.0f * nz * dt - vz;
    float rA = sqrtf(nx * nx + ny * ny + nz * nz);
    float iA = 1.0f / fmaxf(rA, 1e-12f);
    float xA = nx * iA, yA = ny * iA, zA = nz * iA;
    float rB = sqrtf(wx * wx + wy * wy + wz * wz);
    float iB = 1.0f / fmaxf(rB, 1e-12f);
    float xB = wx * iB, yB = wy * iB, zB = wz * iB;
    float e = expf(-rough);

    const float LAM[11] = {3.1415926535897927f, 2.0943951023931957f, 0.7853981633974483f, 0.0f,
                           -0.13089969389957473f, 0.0f, 0.04908738521234052f, 0.0f,
                           -0.024543692606170262f, 0.0f, 0.014317154020265985f};
    const float DF[11] = {1.f, 1.f, 3.f, 15.f, 105.f, 945.f, 10395.f, 135135.f,
                          2027025.f, 34459425.f, 654729075.f};

    float q1A[11], q2A[11], q1B[11], q2B[11];
    float ir0 = 0, ir1 = 0, ir2 = 0, lg0 = 0, lg1 = 0, lg2 = 0;
    float rlA = 1.f, rlB = 1.f, pw = 1.f, dec = 1.f;
    const int pb = blockIdx.x * PF_PTS;

#pragma unroll
    for (int l = 0; l <= 10; ++l) {
        const int CNT = 3 * (2 * l + 1);
        const int BOFF = 3 * l * l;
        __syncthreads();   // previous chunk fully consumed
#pragma unroll 1
        for (int f2 = tid; f2 < PF_PTS * CNT; f2 += 256) {
            int pp = f2 / CNT, off = f2 - pp * CNT;
            int gp = pb + pp;
            stage[pp * CNT + off] = (gp < N) ? refsh[(size_t)gp * 363 + BOFF + off] : 0.f;
        }
        __syncthreads();

        float qcA[11], qcB[11];
        if (l == 0) { qcA[0] = 1.f; qcB[0] = 1.f; }
        else {
            rlA *= rA; rlB *= rB; pw *= e; dec *= pw;
#pragma unroll
            for (int m = 0; m <= 8; ++m) if (m <= l - 2) {
                float inv = 1.f / (float)(l - m);
                qcA[m] = ((float)(2 * l - 1) * zA * q1A[m] - (float)(l + m - 1) * q2A[m]) * inv;
                qcB[m] = ((float)(2 * l - 1) * zB * q1B[m] - (float)(l + m - 1) * q2B[m]) * inv;
            }
            qcA[l - 1] = (float)(2 * l - 1) * zA * q1A[l - 1];
            qcB[l - 1] = (float)(2 * l - 1) * zB * q1B[l - 1];
            qcA[l] = DF[l]; qcB[l] = DF[l];
        }
        const float scA = LAM[l] * rlA;
        const float scB = dec * rlB;
        const float* sp = stage + tid * CNT;
        float kf = sqrtf((float)(2 * l + 1) * 0.07957747154594767f);
        {
            float wA = kf * qcA[0] * scA;
            float wB = kf * qcB[0] * scB;
            float r0 = sp[3 * l + 0], r1 = sp[3 * l + 1], r2 = sp[3 * l + 2];
            ir0 += wA * r0; ir1 += wA * r1; ir2 += wA * r2;
            lg0 += wB * r0; lg1 += wB * r1; lg2 += wB * r2;
        }
        float cmA = 1.f, smA = 0.f, cmB = 1.f, smB = 0.f;
#pragma unroll
        for (int m = 1; m <= 10; ++m) if (m <= l) {
            kf *= rsqrtf((float)((l + m) * (l - m + 1)));
            if (m == 1) kf *= 1.41421356237309515f;
            float tA = xA * cmA - yA * smA; smA = xA * smA + yA * cmA; cmA = tA;
            float tB = xB * cmB - yB * smB; smB = xB * smB + yB * cmB; cmB = tB;
            float gA = kf * qcA[m] * scA;
            float gB = kf * qcB[m] * scB;
            float p0 = sp[3 * (l + m) + 0], p1 = sp[3 * (l + m) + 1], p2 = sp[3 * (l + m) + 2];
            float n0 = sp[3 * (l - m) + 0], n1 = sp[3 * (l - m) + 1], n2 = sp[3 * (l - m) + 2];
            float ca = gA * cmA, sa = gA * smA;
            ir0 += ca * p0 + sa * n0; ir1 += ca * p1 + sa * n1; ir2 += ca * p2 + sa * n2;
            float cb = gB * cmB, sb = gB * smB;
            lg0 += cb * p0 + sb * n0; lg1 += cb * p1 + sb * n1; lg2 += cb * p2 + sb * n2;
        }
#pragma unroll
        for (int m = 0; m <= 10; ++m) if (m <= l) {
            q2A[m] = q1A[m]; q1A[m] = qcA[m];
            q2B[m] = q1B[m]; q1B[m] = qcB[m];
        }
    }

    if (valid) {
        ir0 = fmaxf(ir0, 0.f); ir1 = fmaxf(ir1, 0.f); ir2 = fmaxf(ir2, 0.f);
        lg0 = fmaxf(lg0, 0.f); lg1 = fmaxf(lg1, 0.f); lg2 = fmaxf(lg2, 0.f);
        float a0 = 1.0f / (1.0f + expf(-f10));
        float a1 = 1.0f / (1.0f + expf(-f11));
        float a2 = 1.0f / (1.0f + expf(-f12));
        size_t N3 = (size_t)N * 3;
        out[2 * N3 + 3 * p + 0] = a0 * ir0; out[2 * N3 + 3 * p + 1] = a1 * ir1; out[2 * N3 + 3 * p + 2] = a2 * ir2;
        out[4 * N3 + 3 * p + 0] = lg0;      out[4 * N3 + 3 * p + 1] = lg1;      out[4 * N3 + 3 * p + 2] = lg2;
        out[5 * N3 + 3 * p + 0] = ir0;      out[5 * N3 + 3 * p + 1] = ir1;      out[5 * N3 + 3 * p + 2] = ir2;
    }
}

// ---------------- GEMM helpers ----------------
static __device__ __forceinline__ uint32_t smem_u32(const void* p) {
    return (uint32_t)__cvta_generic_to_shared(p);
}

// ---------------- gemm5: GBK=32, 64x64 warp tiles (measured best for big layers) ----------------
#define GBM 128
#define GBN 128
#define GBK 32
#define GSTG 3
#define SA_STRIDE 40
#define SB_STRIDE 136
#define SA_SIZE (GBM * SA_STRIDE)
#define SB_SIZE (GBK * SB_STRIDE)
#define GEMM_SMEM (GSTG * (SA_SIZE + SB_SIZE) * 2)

__global__ void __launch_bounds__(128, 2) gemm5_kernel(
    const __half* __restrict__ A, const __half* __restrict__ B,
    const float* __restrict__ bias, __half* __restrict__ Ch, float* __restrict__ Cf,
    int M, int K, int ldB, int NoutReal, int doRelu)
{
    extern __shared__ __half hsm[];
    __half* sAb = hsm;
    __half* sBb = hsm + GSTG * SA_SIZE;

    const int tid = threadIdx.x;
    const int warp = tid >> 5, lane = tid & 31;
    const int rowbase = (warp & 1) * 64;
    const int colbase = (warp >> 1) * 64;
    const int n0 = blockIdx.x * GBN;
    const int m0 = blockIdx.y * GBM;

    float acc[4][8][4];
#pragma unroll
    for (int a = 0; a < 4; ++a)
#pragma unroll
        for (int b = 0; b < 8; ++b)
#pragma unroll
            for (int c = 0; c < 4; ++c) acc[a][b][c] = 0.0f;

    const int T = K / GBK;

    auto issue = [&](int t, int buf) {
        int k0 = t * GBK;
        __half* sa = sAb + buf * SA_SIZE;
        __half* sb = sBb + buf * SB_SIZE;
#pragma unroll
        for (int c2 = 0; c2 < 4; ++c2) {
            int ch = tid + c2 * 128;
            int r = ch >> 2, cc = (ch & 3) * 8;
            uint32_t dst = smem_u32(sa + r * SA_STRIDE + cc);
            const __half* src = A + (size_t)(m0 + r) * K + k0 + cc;
            asm volatile("cp.async.cg.shared.global [%0], [%1], 16;\n" :: "r"(dst), "l"(src));
        }
#pragma unroll
        for (int c2 = 0; c2 < 4; ++c2) {
            int ch = tid + c2 * 128;
            int r = ch >> 4, cc = (ch & 15) * 8;
            int col = n0 + cc;
            if (col < ldB) {
                uint32_t dst = smem_u32(sb + r * SB_STRIDE + cc);
                const __half* src = B + (size_t)(k0 + r) * ldB + col;
                asm volatile("cp.async.cg.shared.global [%0], [%1], 16;\n" :: "r"(dst), "l"(src));
            } else {
                *reinterpret_cast<uint4*>(sb + r * SB_STRIDE + cc) = make_uint4(0, 0, 0, 0);
            }
        }
    };

    const int bg = lane >> 3;
    const int brow_in = (bg & 1) * 8 + (lane & 7);
    const int bcol_in = colbase + (bg >> 1) * 8;

#pragma unroll
    for (int s2 = 0; s2 < GSTG - 1; ++s2) {
        if (s2 < T) issue(s2, s2);
        asm volatile("cp.async.commit_group;\n" ::: "memory");
    }

    for (int t = 0; t < T; ++t) {
        int cur = t % GSTG;
        asm volatile("cp.async.wait_group 1;\n" ::: "memory");
        __syncthreads();
        int nt = t + GSTG - 1;
        if (nt < T) issue(nt, nt % GSTG);
        asm volatile("cp.async.commit_group;\n" ::: "memory");

        __half* sa = sAb + cur * SA_SIZE;
        __half* sb = sBb + cur * SB_SIZE;
#pragma unroll
        for (int kk = 0; kk < GBK; kk += 16) {
            uint32_t af[4][4], bf[4][4];
#pragma unroll
            for (int mi = 0; mi < 4; ++mi) {
                uint32_t ad = smem_u32(sa + (rowbase + mi * 16 + (lane & 15)) * SA_STRIDE + kk + (lane >> 4) * 8);
                asm volatile("ldmatrix.sync.aligned.m8n8.x4.shared.b16 {%0,%1,%2,%3}, [%4];\n"
                             : "=r"(af[mi][0]), "=r"(af[mi][1]), "=r"(af[mi][2]), "=r"(af[mi][3])
                             : "r"(ad));
            }
#pragma unroll
            for (int nq = 0; nq < 4; ++nq) {
                uint32_t ad = smem_u32(sb + (kk + brow_in) * SB_STRIDE + bcol_in + nq * 16);
                asm volatile("ldmatrix.sync.aligned.m8n8.x4.trans.shared.b16 {%0,%1,%2,%3}, [%4];\n"
                             : "=r"(bf[nq][0]), "=r"(bf[nq][1]), "=r"(bf[nq][2]), "=r"(bf[nq][3])
                             : "r"(ad));
            }
#pragma unroll
            for (int mi = 0; mi < 4; ++mi)
#pragma unroll
                for (int nq = 0; nq < 4; ++nq) {
                    asm volatile(
                        "mma.sync.aligned.m16n8k16.row.col.f32.f16.f16.f32 "
                        "{%0,%1,%2,%3}, {%4,%5,%6,%7}, {%8,%9}, {%0,%1,%2,%3};\n"
                        : "+f"(acc[mi][2 * nq][0]), "+f"(acc[mi][2 * nq][1]),
                          "+f"(acc[mi][2 * nq][2]), "+f"(acc[mi][2 * nq][3])
                        : "r"(af[mi][0]), "r"(af[mi][1]), "r"(af[mi][2]), "r"(af[mi][3]),
                          "r"(bf[nq][0]), "r"(bf[nq][1]));
                    asm volatile(
                        "mma.sync.aligned.m16n8k16.row.col.f32.f16.f16.f32 "
                        "{%0,%1,%2,%3}, {%4,%5,%6,%7}, {%8,%9}, {%0,%1,%2,%3};\n"
                        : "+f"(acc[mi][2 * nq + 1][0]), "+f"(acc[mi][2 * nq + 1][1]),
                          "+f"(acc[mi][2 * nq + 1][2]), "+f"(acc[mi][2 * nq + 1][3])
                        : "r"(af[mi][0]), "r"(af[mi][1]), "r"(af[mi][2]), "r"(af[mi][3]),
                          "r"(bf[nq][2]), "r"(bf[nq][3]));
                }
        }
    }

#pragma unroll
    for (int mi = 0; mi < 4; ++mi) {
        int row0 = m0 + rowbase + mi * 16 + (lane >> 2);
#pragma unroll
        for (int ni = 0; ni < 8; ++ni) {
            int col = n0 + colbase + ni * 8 + (lane & 3) * 2;
            float bv0 = (col < NoutReal) ? bias[col] : 0.0f;
            float bv1 = (col + 1 < NoutReal) ? bias[col + 1] : 0.0f;
#pragma unroll
            for (int rr2 = 0; rr2 < 2; ++rr2) {
                int row = row0 + rr2 * 8;
                if (row >= M) continue;
                float v0 = acc[mi][ni][rr2 * 2 + 0] + bv0;
                float v1 = acc[mi][ni][rr2 * 2 + 1] + bv1;
                if (doRelu) { v0 = fmaxf(v0, 0.f); v1 = fmaxf(v1, 0.f); }
                if (Ch) {
                    *reinterpret_cast<__half2*>(Ch + (size_t)row * ldB + col) = __floats2half2_rn(v0, v1);
                } else {
                    if (col     < NoutReal) Cf[(size_t)row * ldB + col]     = v0;
                    if (col + 1 < NoutReal) Cf[(size_t)row * ldB + col + 1] = v1;
                }
            }
        }
    }
}

// ---------------- gemm6<32>: GBK=64 narrow-N kernel for the last layer ----------------
#define G6K 64
#define SA6_STRIDE 72
#define SA6_SIZE (128 * SA6_STRIDE)

template <int GBN_>
__global__ void __launch_bounds__(128, 2) gemm6_kernel(
    const __half* __restrict__ A, const __half* __restrict__ B,
    const float* __restrict__ bias, __half* __restrict__ Ch, float* __restrict__ Cf,
    int M, int K, int ldB, int NoutReal, int doRelu)
{
    constexpr int SB6_STRIDE = GBN_ + 8;
    constexpr int SB6_SIZE = G6K * SB6_STRIDE;
    constexpr int NQ = (GBN_ == 128) ? 4 : 1;
    constexpr int NI = 2 * NQ;
    constexpr int COLW = (GBN_ == 128) ? 64 : 16;

    extern __shared__ __half hsm[];
    __half* sAb = hsm;
    __half* sBb = hsm + GSTG * SA6_SIZE;

    const int tid = threadIdx.x;
    const int warp = tid >> 5, lane = tid & 31;
    const int rowbase = (warp & 1) * 64;
    const int colbase = (warp >> 1) * COLW;
    const int n0 = blockIdx.x * GBN_;
    const int m0 = blockIdx.y * GBM;

    float acc[4][NI][4];
#pragma unroll
    for (int a = 0; a < 4; ++a)
#pragma unroll
        for (int b = 0; b < NI; ++b)
#pragma unroll
            for (int c = 0; c < 4; ++c) acc[a][b][c] = 0.0f;

    const int T = K / G6K;

    auto issue = [&](int t, int buf) {
        int k0 = t * G6K;
        __half* sa = sAb + buf * SA6_SIZE;
        __half* sb = sBb + buf * SB6_SIZE;
#pragma unroll
        for (int c2 = 0; c2 < 8; ++c2) {
            int ch = tid + c2 * 128;
            int r = ch >> 3, cc = (ch & 7) * 8;
            uint32_t dst = smem_u32(sa + r * SA6_STRIDE + cc);
            const __half* src = A + (size_t)(m0 + r) * K + k0 + cc;
            asm volatile("cp.async.cg.shared.global [%0], [%1], 16;\n" :: "r"(dst), "l"(src));
        }
#pragma unroll
        for (int c2 = 0; c2 < (G6K * GBN_ / 8) / 128; ++c2) {
            int ch = tid + c2 * 128;
            int r = ch / (GBN_ / 8), cc = (ch % (GBN_ / 8)) * 8;
            uint32_t dst = smem_u32(sb + r * SB6_STRIDE + cc);
            const __half* src = B + (size_t)(k0 + r) * ldB + n0 + cc;
            asm volatile("cp.async.cg.shared.global [%0], [%1], 16;\n" :: "r"(dst), "l"(src));
        }
    };

    const int bg = lane >> 3;
    const int brow_in = (bg & 1) * 8 + (lane & 7);
    const int bcol_in = colbase + (bg >> 1) * 8;

#pragma unroll
    for (int s2 = 0; s2 < GSTG - 1; ++s2) {
        if (s2 < T) issue(s2, s2);
        asm volatile("cp.async.commit_group;\n" ::: "memory");
    }

    for (int t = 0; t < T; ++t) {
        int cur = t % GSTG;
        asm volatile("cp.async.wait_group 1;\n" ::: "memory");
        __syncthreads();
        int nt = t + GSTG - 1;
        if (nt < T) issue(nt, nt % GSTG);
        asm volatile("cp.async.commit_group;\n" ::: "memory");

        __half* sa = sAb + cur * SA6_SIZE;
        __half* sb = sBb + cur * SB6_SIZE;
#pragma unroll
        for (int kk = 0; kk < G6K; kk += 16) {
            uint32_t af[4][4], bf[NQ][4];
#pragma unroll
            for (int mi = 0; mi < 4; ++mi) {
                uint32_t ad = smem_u32(sa + (rowbase + mi * 16 + (lane & 15)) * SA6_STRIDE + kk + (lane >> 4) * 8);
                asm volatile("ldmatrix.sync.aligned.m8n8.x4.shared.b16 {%0,%1,%2,%3}, [%4];\n"
                             : "=r"(af[mi][0]), "=r"(af[mi][1]), "=r"(af[mi][2]), "=r"(af[mi][3])
                             : "r"(ad));
            }
#pragma unroll
            for (int nq = 0; nq < NQ; ++nq) {
                uint32_t ad = smem_u32(sb + (kk + brow_in) * SB6_STRIDE + bcol_in + nq * 16);
                asm volatile("ldmatrix.sync.aligned.m8n8.x4.trans.shared.b16 {%0,%1,%2,%3}, [%4];\n"
                             : "=r"(bf[nq][0]), "=r"(bf[nq][1]), "=r"(bf[nq][2]), "=r"(bf[nq][3])
                             : "r"(ad));
            }
#pragma unroll
            for (int mi = 0; mi < 4; ++mi)
#pragma unroll
                for (int nq = 0; nq < NQ; ++nq) {
                    asm volatile(
                        "mma.sync.aligned.m16n8k16.row.col.f32.f16.f16.f32 "
                        "{%0,%1,%2,%3}, {%4,%5,%6,%7}, {%8,%9}, {%0,%1,%2,%3};\n"
                        : "+f"(acc[mi][2 * nq][0]), "+f"(acc[mi][2 * nq][1]),
                          "+f"(acc[mi][2 * nq][2]), "+f"(acc[mi][2 * nq][3])
                        : "r"(af[mi][0]), "r"(af[mi][1]), "r"(af[mi][2]), "r"(af[mi][3]),
                          "r"(bf[nq][0]), "r"(bf[nq][1]));
                    asm volatile(
                        "mma.sync.aligned.m16n8k16.row.col.f32.f16.f16.f32 "
                        "{%0,%1,%2,%3}, {%4,%5,%6,%7}, {%8,%9}, {%0,%1,%2,%3};\n"
                        : "+f"(acc[mi][2 * nq + 1][0]), "+f"(acc[mi][2 * nq + 1][1]),
                          "+f"(acc[mi][2 * nq + 1][2]), "+f"(acc[mi][2 * nq + 1][3])
                        : "r"(af[mi][0]), "r"(af[mi][1]), "r"(af[mi][2]), "r"(af[mi][3]),
                          "r"(bf[nq][2]), "r"(bf[nq][3]));
                }
        }
    }

#pragma unroll
    for (int mi = 0; mi < 4; ++mi) {
        int row0 = m0 + rowbase + mi * 16 + (lane >> 2);
#pragma unroll
        for (int ni = 0; ni < NI; ++ni) {
            int col = n0 + colbase + ni * 8 + (lane & 3) * 2;
            float bv0 = (col < NoutReal) ? bias[col] : 0.0f;
            float bv1 = (col + 1 < NoutReal) ? bias[col + 1] : 0.0f;
#pragma unroll
            for (int rr2 = 0; rr2 < 2; ++rr2) {
                int row = row0 + rr2 * 8;
                if (row >= M) continue;
                float v0 = acc[mi][ni][rr2 * 2 + 0] + bv0;
                float v1 = acc[mi][ni][rr2 * 2 + 1] + bv1;
                if (doRelu) { v0 = fmaxf(v0, 0.f); v1 = fmaxf(v1, 0.f); }
                if (Ch) {
                    *reinterpret_cast<__half2*>(Ch + (size_t)row * ldB + col) = __floats2half2_rn(v0, v1);
                } else {
                    if (col     < NoutReal) Cf[(size_t)row * ldB + col]     = v0;
                    if (col + 1 < NoutReal) Cf[(size_t)row * ldB + col + 1] = v1;
                }
            }
        }
    }
}

// ---------------- final ----------------
__global__ void __launch_bounds__(256) final_kernel(const float* __restrict__ feat, float* out, int N)
{
    int i = blockIdx.x * blockDim.x + threadIdx.x;
    if (i >= N) return;
    const float* cs = g_cs + (size_t)i * 32;
    const float* f = feat + (size_t)i * 16;
    float rr = 0.f, gg = 0.f, bb = 0.f;
#pragma unroll
    for (int j = 0; j < 9; ++j) {
        float cj = f[1 + j];
        rr += cs[j] * cj;
        gg += cs[9 + j] * cj;
        bb += cs[18 + j] * cj;
    }
    float gate0 = 1.0f / (1.0f + expf(-rr));
    float gate1 = 1.0f / (1.0f + expf(-gg));
    float gate2 = 1.0f / (1.0f + expf(-bb));
    float sp0 = 1.0f / (1.0f + expf(-f[13]));
    float sp1 = 1.0f / (1.0f + expf(-f[14]));
    float sp2 = 1.0f / (1.0f + expf(-f[15]));
    size_t N3 = (size_t)N * 3;
    float l0 = out[4 * N3 + 3 * i + 0], l1 = out[4 * N3 + 3 * i + 1], l2 = out[4 * N3 + 3 * i + 2];
    float d0 = out[2 * N3 + 3 * i + 0], d1 = out[2 * N3 + 3 * i + 1], d2 = out[2 * N3 + 3 * i + 2];
    float s0 = sp0 * l0 * gate0, s1 = sp1 * l1 * gate1, s2 = sp2 * l2 * gate2;
    out[3 * N3 + 3 * i + 0] = s0; out[3 * N3 + 3 * i + 1] = s1; out[3 * N3 + 3 * i + 2] = s2;
    out[3 * i + 0] = d0 + s0; out[3 * i + 1] = d1 + s1; out[3 * i + 2] = d2 + s2;
}

// ---------------- launch ----------------
extern "C" void kernel_launch(void* const* d_in, const int* in_sizes, int n_in,
                              void* d_out, int out_size)
{
    const float* normals = (const float*)d_in[0];
    const float* viewd   = (const float*)d_in[1];
    const float* feat    = (const float*)d_in[2];
    const float* refsh   = (const float*)d_in[3];
    const float* w0 = (const float*)d_in[4];  const float* b0 = (const float*)d_in[5];
    const float* w1 = (const float*)d_in[6];  const float* b1 = (const float*)d_in[7];
    const float* w2 = (const float*)d_in[8];  const float* b2 = (const float*)d_in[9];
    const float* w3 = (const float*)d_in[10]; const float* b3 = (const float*)d_in[11];
    const float* wc = (const float*)d_in[12]; const float* bc = (const float*)d_in[13];
    float* out = (float*)d_out;

    int N = in_sizes[0] / 3;
    if (N > MAXN) N = MAXN;

    void* p;
    cudaGetSymbolAddress(&p, g_hin);  __half* hin  = (__half*)p;
    cudaGetSymbolAddress(&p, g_actA); __half* actA = (__half*)p;
    cudaGetSymbolAddress(&p, g_actB); __half* actB = (__half*)p;
    cudaGetSymbolAddress(&p, g_cs);   float*  cs   = (float*)p;
    cudaGetSymbolAddress(&p, g_w0c);  __half* w0c  = (__half*)p;
    cudaGetSymbolAddress(&p, g_w1c);  __half* w1c  = (__half*)p;
    cudaGetSymbolAddress(&p, g_w2c);  __half* w2c  = (__half*)p;
    cudaGetSymbolAddress(&p, g_w3c);  __half* w3c  = (__half*)p;
    cudaGetSymbolAddress(&p, g_wcc);  __half* wcc  = (__half*)p;

    const int SM6_SMALL = GSTG * (SA6_SIZE + G6K * 40) * 2;
    cudaFuncSetAttribute(gemm5_kernel,      cudaFuncAttributeMaxDynamicSharedMemorySize, GEMM_SMEM);
    cudaFuncSetAttribute(gemm6_kernel<32>,  cudaFuncAttributeMaxDynamicSharedMemorySize, SM6_SMALL);
    cudaFuncSetAttribute(prep_fused_kernel, cudaFuncAttributeMaxDynamicSharedMemorySize, PF_SMEM);

    // ONE side stream + 3 events (within the teardown-safe footprint).
    cudaStream_t sB;
    cudaStreamCreateWithFlags(&sB, cudaStreamNonBlocking);
    cudaEvent_t evRoot, evConv, evDot;
    cudaEventCreateWithFlags(&evRoot, cudaEventDisableTiming);
    cudaEventCreateWithFlags(&evConv, cudaEventDisableTiming);
    cudaEventCreateWithFlags(&evDot,  cudaEventDisableTiming);

    dim3 blk(128);
    dim3 gBig(4, (N + GBM - 1) / GBM);
    dim3 gLast(1, (N + GBM - 1) / GBM);

    cudaEventRecord(evRoot, 0);
    cudaStreamWaitEvent(sB, evRoot, 0);

    // side stream: convert -> prep_fused
    convert_weights_kernel<<<(512 * 512 + 255) / 256, 256, 0, sB>>>(w0, w1, w2, w3, wc);        // #1 (sB)
    cudaEventRecord(evConv, sB);

    hin_kernel<<<(N + 255) / 256, 256>>>(normals, viewd, feat, out, N);                         // #2 (main)

    cudaStreamWaitEvent(0, evConv, 0);
    gemm5_kernel<<<gBig, blk, GEMM_SMEM>>>(hin,  w0c, b0, actA, nullptr, N, 32,  512, 512, 1);  // #3 (L0)
    gemm5_kernel<<<gBig, blk, GEMM_SMEM>>>(actA, w1c, b1, actB, nullptr, N, 512, 512, 512, 1);  // #4 (L1) <- profiled

    prep_fused_kernel<<<(N + PF_PTS - 1) / PF_PTS, 256, PF_SMEM, sB>>>(normals, viewd, feat, refsh, out, N); // #5 (sB)
    cudaEventRecord(evDot, sB);

    gemm5_kernel<<<gBig, blk, GEMM_SMEM>>>(actB, w2c, b2, actA, nullptr, N, 512, 512, 512, 1);  // #6 (L2)
    gemm5_kernel<<<gBig, blk, GEMM_SMEM>>>(actA, w3c, b3, actB, nullptr, N, 512, 512, 512, 1);  // #7 (L3)
    gemm6_kernel<32><<<gLast, blk, SM6_SMALL>>>(actB, wcc, bc, nullptr, cs, N, 512, 32, 27, 0); // #8 (L4)

    cudaStreamWaitEvent(0, evDot, 0);
    final_kernel<<<(N + 255) / 256, 256>>>(feat, out, N);                                       // #9
}